// round 2
// baseline (speedup 1.0000x reference)
#include <cuda_runtime.h>
#include <cuda_bf16.h>
#include <math.h>

// Problem constants (fixed-shape problem)
#define MAXN 50048
#define MAXE 1600000
#define HID 128
#define NH 8
#define HD 16

// ---------------- device scratch (no allocation allowed) ----------------
__device__ float g_Q[MAXN * HID];
__device__ float g_K[MAXN * HID];
__device__ float g_V[MAXN * HID];
__device__ int g_cnt[MAXN];
__device__ int g_off[MAXN];
__device__ int g_cur[MAXN];
__device__ int g_esrc[MAXE];

// ---------------- QKV GEMM: C[n,128] = h[n,128] @ W[128,128] + b --------
// Tile 128x128, BK=8, 256 threads, 8x8 microtile per thread.
__global__ __launch_bounds__(256) void qkv_gemm(
    const float* __restrict__ h,
    const float* __restrict__ wq, const float* __restrict__ bq,
    const float* __restrict__ wk, const float* __restrict__ bk,
    const float* __restrict__ wv, const float* __restrict__ bv,
    int n)
{
    const float* W; const float* bias; float* out;
    if (blockIdx.y == 0)      { W = wq; bias = bq; out = g_Q; }
    else if (blockIdx.y == 1) { W = wk; bias = bk; out = g_K; }
    else                      { W = wv; bias = bv; out = g_V; }

    __shared__ float As[8][128];  // As[k][m] (transposed)
    __shared__ float Bs[8][128];  // Bs[k][c]

    const int tid  = threadIdx.x;          // 0..255
    const int row0 = blockIdx.x * 128;
    const int tr   = (tid / 16) * 8;       // microtile row start (0..120)
    const int tc   = (tid % 16) * 8;       // microtile col start (0..120)

    float acc[8][8];
#pragma unroll
    for (int i = 0; i < 8; i++)
#pragma unroll
        for (int j = 0; j < 8; j++) acc[i][j] = 0.f;

    for (int kk = 0; kk < HID; kk += 8) {
        // A tile: 128 rows x 8 k -> 1024 floats, 4 per thread (one float4)
        {
            int m  = tid >> 1;             // 0..127
            int k4 = (tid & 1) * 4;        // 0 or 4
            float4 v = make_float4(0.f, 0.f, 0.f, 0.f);
            int row = row0 + m;
            if (row < n)
                v = *(const float4*)(h + (size_t)row * HID + kk + k4);
            As[k4 + 0][m] = v.x;
            As[k4 + 1][m] = v.y;
            As[k4 + 2][m] = v.z;
            As[k4 + 3][m] = v.w;
        }
        // B tile: 8 k x 128 cols
        {
            int k  = tid >> 5;             // 0..7
            int c4 = (tid & 31) * 4;       // 0..124
            float4 v = *(const float4*)(W + (size_t)(kk + k) * 128 + c4);
            *(float4*)&Bs[k][c4] = v;
        }
        __syncthreads();

#pragma unroll
        for (int k = 0; k < 8; k++) {
            float a[8], b[8];
#pragma unroll
            for (int i = 0; i < 8; i++) a[i] = As[k][tr + i];
#pragma unroll
            for (int j = 0; j < 8; j++) b[j] = Bs[k][tc + j];
#pragma unroll
            for (int i = 0; i < 8; i++)
#pragma unroll
                for (int j = 0; j < 8; j++) acc[i][j] = fmaf(a[i], b[j], acc[i][j]);
        }
        __syncthreads();
    }

    // epilogue: add bias, store
    float b0[8];
#pragma unroll
    for (int j = 0; j < 8; j++) b0[j] = bias[tc + j];
#pragma unroll
    for (int i = 0; i < 8; i++) {
        int row = row0 + tr + i;
        if (row < n) {
            float4 o0, o1;
            o0.x = acc[i][0] + b0[0]; o0.y = acc[i][1] + b0[1];
            o0.z = acc[i][2] + b0[2]; o0.w = acc[i][3] + b0[3];
            o1.x = acc[i][4] + b0[4]; o1.y = acc[i][5] + b0[5];
            o1.z = acc[i][6] + b0[6]; o1.w = acc[i][7] + b0[7];
            *(float4*)(out + (size_t)row * 128 + tc)     = o0;
            *(float4*)(out + (size_t)row * 128 + tc + 4) = o1;
        }
    }
}

// ---------------- CSR construction --------------------------------------
__global__ void zero_cnt(int n)
{
    int i = blockIdx.x * blockDim.x + threadIdx.x;
    if (i < n) g_cnt[i] = 0;
}

__global__ void hist_kernel(const int* __restrict__ dst, int E)
{
    int i = blockIdx.x * blockDim.x + threadIdx.x;
    if (i < E) atomicAdd(&g_cnt[dst[i]], 1);
}

__global__ __launch_bounds__(1024) void scan_kernel(int n)
{
    __shared__ int sums[1024];
    int tid = threadIdx.x;
    int per = (n + 1023) / 1024;
    int s0 = tid * per;
    int s1 = min(s0 + per, n);
    int local = 0;
    for (int i = s0; i < s1; i++) local += g_cnt[i];
    sums[tid] = local;
    __syncthreads();
    // inclusive Hillis-Steele scan
    for (int off = 1; off < 1024; off <<= 1) {
        int v = 0;
        if (tid >= off) v = sums[tid - off];
        __syncthreads();
        sums[tid] += v;
        __syncthreads();
    }
    int run = (tid == 0) ? 0 : sums[tid - 1];
    for (int i = s0; i < s1; i++) {
        g_off[i] = run;
        g_cur[i] = run;
        run += g_cnt[i];
    }
}

__global__ void scatter_kernel(const int* __restrict__ src,
                               const int* __restrict__ dst, int E)
{
    int i = blockIdx.x * blockDim.x + threadIdx.x;
    if (i < E) {
        int p = atomicAdd(&g_cur[dst[i]], 1);
        g_esrc[p] = src[i];
    }
}

// ---------------- gather: one warp per destination node ------------------
// lane l owns dims [l*4, l*4+4). head = l/4 (4 lanes x 4 dims = 16 dims/head).
__global__ __launch_bounds__(256) void gat_gather(float* __restrict__ out, int n)
{
    int warp = (blockIdx.x * blockDim.x + threadIdx.x) >> 5;
    int lane = threadIdx.x & 31;
    if (warp >= n) return;

    const int t = lane * 4;
    const int start = g_off[warp];
    const int end   = g_cur[warp];   // == g_off + count after scatter

    const float4 q = *(const float4*)(g_Q + (size_t)warp * 128 + t);

    float ax = 0.f, ay = 0.f, az = 0.f, aw = 0.f;
    float den = 0.f;

    int s_next = (start < end) ? g_esrc[start] : 0;
    for (int i = start; i < end; i++) {
        int s = s_next;                    // uniform across warp (broadcast)
        if (i + 1 < end) s_next = g_esrc[i + 1];   // prefetch next index
        const float4 k4 = *(const float4*)(g_K + (size_t)s * 128 + t);
        float p = q.x * k4.x + q.y * k4.y + q.z * k4.z + q.w * k4.w;
        // reduce across the 4 lanes of this head
        p += __shfl_xor_sync(0xFFFFFFFFu, p, 1);
        p += __shfl_xor_sync(0xFFFFFFFFu, p, 2);
        float e = __expf(p * 0.25f);       // 1/sqrt(D), D=16
        const float4 v4 = *(const float4*)(g_V + (size_t)s * 128 + t);
        ax = fmaf(e, v4.x, ax);
        ay = fmaf(e, v4.y, ay);
        az = fmaf(e, v4.z, az);
        aw = fmaf(e, v4.w, aw);
        den += e;                          // identical across the 4 lanes
    }

    float inv = 1.f / den;
    float4 o;
    o.x = ax * inv; o.y = ay * inv; o.z = az * inv; o.w = aw * inv;
    *(float4*)(out + (size_t)warp * 128 + t) = o;
}

// ---------------- launch ------------------------------------------------
extern "C" void kernel_launch(void* const* d_in, const int* in_sizes, int n_in,
                              void* d_out, int out_size)
{
    const float* h  = (const float*)d_in[0];
    const float* wq = (const float*)d_in[1];
    const float* bq = (const float*)d_in[2];
    const float* wk = (const float*)d_in[3];
    const float* bk = (const float*)d_in[4];
    const float* wv = (const float*)d_in[5];
    const float* bv = (const float*)d_in[6];
    const int*  src = (const int*)d_in[7];
    const int*  dst = (const int*)d_in[8];

    const int n = in_sizes[0] / HID;
    const int E = in_sizes[7];

    float* out = (float*)d_out;

    // 1) Q,K,V GEMMs
    {
        dim3 grid((n + 127) / 128, 3);
        qkv_gemm<<<grid, 256>>>(h, wq, bq, wk, bk, wv, bv, n);
    }
    // 2) CSR build
    zero_cnt<<<(n + 255) / 256, 256>>>(n);
    hist_kernel<<<(E + 255) / 256, 256>>>(dst, E);
    scan_kernel<<<1, 1024>>>(n);
    scatter_kernel<<<(E + 255) / 256, 256>>>(src, dst, E);
    // 3) gather (one warp per node, 8 warps/block)
    gat_gather<<<(n + 7) / 8, 256>>>(out, n);
}

// round 3
// speedup vs baseline: 1.2623x; 1.2623x over previous
#include <cuda_runtime.h>
#include <cuda_bf16.h>
#include <math.h>

// Problem constants (fixed-shape problem)
#define MAXN 50048
#define MAXE 1600000
#define HID 128
#define NH 8
#define HD 16
#define SCAN_BLK 256

// ---------------- device scratch (no allocation allowed) ----------------
__device__ float g_Q[MAXN * HID];
__device__ float g_K[MAXN * HID];
__device__ float g_V[MAXN * HID];
__device__ int g_cnt[MAXN];
__device__ int g_off[MAXN];
__device__ int g_cur[MAXN];
__device__ int g_esrc[MAXE];
__device__ int g_bsum[512];

// ---------------- QKV GEMM: C[n,128] = h[n,128] @ W[128,128] + b --------
// Tile 128x128, BK=8, 256 threads, 8x8 microtile per thread.
__global__ __launch_bounds__(256) void qkv_gemm(
    const float* __restrict__ h,
    const float* __restrict__ wq, const float* __restrict__ bq,
    const float* __restrict__ wk, const float* __restrict__ bk,
    const float* __restrict__ wv, const float* __restrict__ bv,
    int n)
{
    const float* W; const float* bias; float* out;
    if (blockIdx.y == 0)      { W = wq; bias = bq; out = g_Q; }
    else if (blockIdx.y == 1) { W = wk; bias = bk; out = g_K; }
    else                      { W = wv; bias = bv; out = g_V; }

    __shared__ float As[8][128];  // As[k][m] (transposed)
    __shared__ float Bs[8][128];  // Bs[k][c]

    const int tid  = threadIdx.x;          // 0..255
    const int row0 = blockIdx.x * 128;
    const int tr   = (tid / 16) * 8;       // microtile row start (0..120)
    const int tc   = (tid % 16) * 8;       // microtile col start (0..120)

    float acc[8][8];
#pragma unroll
    for (int i = 0; i < 8; i++)
#pragma unroll
        for (int j = 0; j < 8; j++) acc[i][j] = 0.f;

    for (int kk = 0; kk < HID; kk += 8) {
        {
            int m  = tid >> 1;             // 0..127
            int k4 = (tid & 1) * 4;        // 0 or 4
            float4 v = make_float4(0.f, 0.f, 0.f, 0.f);
            int row = row0 + m;
            if (row < n)
                v = *(const float4*)(h + (size_t)row * HID + kk + k4);
            As[k4 + 0][m] = v.x;
            As[k4 + 1][m] = v.y;
            As[k4 + 2][m] = v.z;
            As[k4 + 3][m] = v.w;
        }
        {
            int k  = tid >> 5;             // 0..7
            int c4 = (tid & 31) * 4;       // 0..124
            float4 v = *(const float4*)(W + (size_t)(kk + k) * 128 + c4);
            *(float4*)&Bs[k][c4] = v;
        }
        __syncthreads();

#pragma unroll
        for (int k = 0; k < 8; k++) {
            float a[8], b[8];
#pragma unroll
            for (int i = 0; i < 8; i++) a[i] = As[k][tr + i];
#pragma unroll
            for (int j = 0; j < 8; j++) b[j] = Bs[k][tc + j];
#pragma unroll
            for (int i = 0; i < 8; i++)
#pragma unroll
                for (int j = 0; j < 8; j++) acc[i][j] = fmaf(a[i], b[j], acc[i][j]);
        }
        __syncthreads();
    }

    float b0[8];
#pragma unroll
    for (int j = 0; j < 8; j++) b0[j] = bias[tc + j];
#pragma unroll
    for (int i = 0; i < 8; i++) {
        int row = row0 + tr + i;
        if (row < n) {
            float4 o0, o1;
            o0.x = acc[i][0] + b0[0]; o0.y = acc[i][1] + b0[1];
            o0.z = acc[i][2] + b0[2]; o0.w = acc[i][3] + b0[3];
            o1.x = acc[i][4] + b0[4]; o1.y = acc[i][5] + b0[5];
            o1.z = acc[i][6] + b0[6]; o1.w = acc[i][7] + b0[7];
            *(float4*)(out + (size_t)row * 128 + tc)     = o0;
            *(float4*)(out + (size_t)row * 128 + tc + 4) = o1;
        }
    }
}

// ---------------- CSR construction --------------------------------------
__global__ void zero_cnt(int n)
{
    int i = blockIdx.x * blockDim.x + threadIdx.x;
    if (i < n) g_cnt[i] = 0;
}

__global__ void hist_kernel(const int* __restrict__ dst, int E)
{
    int i = blockIdx.x * blockDim.x + threadIdx.x;
    if (i < E) atomicAdd(&g_cnt[dst[i]], 1);
}

// Stage 1: per-block reduction of g_cnt chunks (SCAN_BLK elems per block)
__global__ __launch_bounds__(SCAN_BLK) void scan_partial(int n)
{
    __shared__ int sh[SCAN_BLK];
    int i = blockIdx.x * SCAN_BLK + threadIdx.x;
    int v = (i < n) ? g_cnt[i] : 0;
    sh[threadIdx.x] = v;
    __syncthreads();
    for (int off = SCAN_BLK / 2; off > 0; off >>= 1) {
        if (threadIdx.x < off) sh[threadIdx.x] += sh[threadIdx.x + off];
        __syncthreads();
    }
    if (threadIdx.x == 0) g_bsum[blockIdx.x] = sh[0];
}

// Stage 2: single-block exclusive scan of block sums (nb <= 256)
__global__ __launch_bounds__(SCAN_BLK) void scan_bsums(int nb)
{
    __shared__ int sh[SCAN_BLK];
    int t = threadIdx.x;
    int v = (t < nb) ? g_bsum[t] : 0;
    sh[t] = v;
    __syncthreads();
    // inclusive Hillis-Steele
    for (int off = 1; off < SCAN_BLK; off <<= 1) {
        int u = (t >= off) ? sh[t - off] : 0;
        __syncthreads();
        sh[t] += u;
        __syncthreads();
    }
    if (t < nb) g_bsum[t] = sh[t] - v;   // exclusive
}

// Stage 3: per-block exclusive scan of chunk + block offset -> g_off/g_cur
__global__ __launch_bounds__(SCAN_BLK) void scan_final(int n)
{
    __shared__ int sh[SCAN_BLK];
    int i = blockIdx.x * SCAN_BLK + threadIdx.x;
    int t = threadIdx.x;
    int v = (i < n) ? g_cnt[i] : 0;
    sh[t] = v;
    __syncthreads();
    for (int off = 1; off < SCAN_BLK; off <<= 1) {
        int u = (t >= off) ? sh[t - off] : 0;
        __syncthreads();
        sh[t] += u;
        __syncthreads();
    }
    if (i < n) {
        int excl = sh[t] - v + g_bsum[blockIdx.x];
        g_off[i] = excl;
        g_cur[i] = excl;
    }
}

__global__ void scatter_kernel(const int* __restrict__ src,
                               const int* __restrict__ dst, int E)
{
    int i = blockIdx.x * blockDim.x + threadIdx.x;
    if (i < E) {
        int p = atomicAdd(&g_cur[dst[i]], 1);
        g_esrc[p] = src[i];
    }
}

// ---------------- gather: one warp per destination node ------------------
// lane l owns dims [l*4, l*4+4). head = l/4 (4 lanes x 4 dims = 16 dims/head).
__global__ __launch_bounds__(256) void gat_gather(float* __restrict__ out, int n)
{
    int warp = (blockIdx.x * blockDim.x + threadIdx.x) >> 5;
    int lane = threadIdx.x & 31;
    if (warp >= n) return;

    const int t = lane * 4;
    const int start = g_off[warp];
    const int end   = g_cur[warp];   // == g_off + count after scatter

    const float4 q = *(const float4*)(g_Q + (size_t)warp * 128 + t);

    float ax = 0.f, ay = 0.f, az = 0.f, aw = 0.f;
    float den = 0.f;

    int s_next = (start < end) ? g_esrc[start] : 0;
    for (int i = start; i < end; i++) {
        int s = s_next;                    // uniform across warp (broadcast)
        if (i + 1 < end) s_next = g_esrc[i + 1];   // prefetch next index
        const float4 k4 = *(const float4*)(g_K + (size_t)s * 128 + t);
        float p = q.x * k4.x + q.y * k4.y + q.z * k4.z + q.w * k4.w;
        p += __shfl_xor_sync(0xFFFFFFFFu, p, 1);
        p += __shfl_xor_sync(0xFFFFFFFFu, p, 2);
        float e = __expf(p * 0.25f);       // 1/sqrt(D), D=16
        const float4 v4 = *(const float4*)(g_V + (size_t)s * 128 + t);
        ax = fmaf(e, v4.x, ax);
        ay = fmaf(e, v4.y, ay);
        az = fmaf(e, v4.z, az);
        aw = fmaf(e, v4.w, aw);
        den += e;
    }

    float inv = 1.f / den;
    float4 o;
    o.x = ax * inv; o.y = ay * inv; o.z = az * inv; o.w = aw * inv;
    *(float4*)(out + (size_t)warp * 128 + t) = o;
}

// ---------------- launch ------------------------------------------------
extern "C" void kernel_launch(void* const* d_in, const int* in_sizes, int n_in,
                              void* d_out, int out_size)
{
    const float* h  = (const float*)d_in[0];
    const float* wq = (const float*)d_in[1];
    const float* bq = (const float*)d_in[2];
    const float* wk = (const float*)d_in[3];
    const float* bk = (const float*)d_in[4];
    const float* wv = (const float*)d_in[5];
    const float* bv = (const float*)d_in[6];
    const int*  src = (const int*)d_in[7];
    const int*  dst = (const int*)d_in[8];

    const int n = in_sizes[0] / HID;
    const int E = in_sizes[7];
    const int nb = (n + SCAN_BLK - 1) / SCAN_BLK;

    float* out = (float*)d_out;

    // 1) Q,K,V GEMMs
    {
        dim3 grid((n + 127) / 128, 3);
        qkv_gemm<<<grid, 256>>>(h, wq, bq, wk, bk, wv, bv, n);
    }
    // 2) CSR build (parallel 3-stage scan)
    zero_cnt<<<(n + 255) / 256, 256>>>(n);
    hist_kernel<<<(E + 255) / 256, 256>>>(dst, E);
    scan_partial<<<nb, SCAN_BLK>>>(n);
    scan_bsums<<<1, SCAN_BLK>>>(nb);
    scan_final<<<nb, SCAN_BLK>>>(n);
    scatter_kernel<<<(E + 255) / 256, 256>>>(src, dst, E);
    // 3) gather (one warp per node, 8 warps/block)
    gat_gather<<<(n + 7) / 8, 256>>>(out, n);
}

// round 4
// speedup vs baseline: 1.5478x; 1.2262x over previous
#include <cuda_runtime.h>
#include <cuda_bf16.h>
#include <math.h>

// Problem constants (fixed-shape problem)
#define MAXN 50048
#define MAXE 1600000
#define HID 128
#define NH 8
#define HD 16
#define SCAN_BLK 256

// ---------------- device scratch (no allocation allowed) ----------------
__device__ float g_Q[MAXN * HID];
__device__ float g_K[MAXN * HID];
__device__ float g_V[MAXN * HID];
__device__ int g_cnt[MAXN];
__device__ int g_off[MAXN];
__device__ int g_cur[MAXN];
__device__ int g_esrc[MAXE];
__device__ int g_bsum[512];

// ---------------- QKV GEMM (tf32 tensor cores) ---------------------------
// C[n,128] = h[n,128] @ W[128,128] + b.  Block tile 128x128, BK=32.
// 256 threads = 8 warps in 2(M) x 4(N); warp tile 64x32; mma.m16n8k8.tf32.
__device__ __forceinline__ unsigned cvt_tf32(float v)
{
    unsigned r;
    asm("cvt.rna.tf32.f32 %0, %1;" : "=r"(r) : "f"(v));
    return r;
}

__global__ __launch_bounds__(256) void qkv_gemm(
    const float* __restrict__ h,
    const float* __restrict__ wq, const float* __restrict__ bq,
    const float* __restrict__ wk, const float* __restrict__ bk,
    const float* __restrict__ wv, const float* __restrict__ bv,
    int n)
{
    const float* W; const float* bias; float* out;
    if (blockIdx.y == 0)      { W = wq; bias = bq; out = g_Q; }
    else if (blockIdx.y == 1) { W = wk; bias = bk; out = g_K; }
    else                      { W = wv; bias = bv; out = g_V; }

    __shared__ float As[32][132];   // [k][m], tf32-rounded
    __shared__ float Bs[32][132];   // [k][n], tf32-rounded

    const int tid  = threadIdx.x;
    const int lane = tid & 31;
    const int wid  = tid >> 5;          // 0..7
    const int wm   = wid >> 2;          // 0..1 -> M offset wm*64
    const int wn   = wid & 3;           // 0..3 -> N offset wn*32
    const int g    = lane >> 2;         // groupID 0..7
    const int tg   = lane & 3;          // thread-in-group 0..3
    const int row0 = blockIdx.x * 128;

    float c[4][4][4];
#pragma unroll
    for (int mi = 0; mi < 4; mi++)
#pragma unroll
        for (int ni = 0; ni < 4; ni++)
#pragma unroll
            for (int r = 0; r < 4; r++) c[mi][ni][r] = 0.f;

    for (int kk = 0; kk < HID; kk += 32) {
        // load A chunk: 128 rows x 32 k. thread: row=tid>>1, 16 cols.
        {
            int m    = tid >> 1;
            int base = (tid & 1) * 16;
            int row  = row0 + m;
#pragma unroll
            for (int i = 0; i < 4; i++) {
                float4 v = make_float4(0.f, 0.f, 0.f, 0.f);
                if (row < n)
                    v = *(const float4*)(h + (size_t)row * HID + kk + base + i * 4);
                As[base + i * 4 + 0][m] = __uint_as_float(cvt_tf32(v.x));
                As[base + i * 4 + 1][m] = __uint_as_float(cvt_tf32(v.y));
                As[base + i * 4 + 2][m] = __uint_as_float(cvt_tf32(v.z));
                As[base + i * 4 + 3][m] = __uint_as_float(cvt_tf32(v.w));
            }
        }
        // load B chunk: 32 k x 128 n. thread: k=tid>>3, 16 cols.
        {
            int k    = tid >> 3;
            int base = (tid & 7) * 16;
#pragma unroll
            for (int i = 0; i < 4; i++) {
                float4 v = *(const float4*)(W + (size_t)(kk + k) * 128 + base + i * 4);
                Bs[k][base + i * 4 + 0] = __uint_as_float(cvt_tf32(v.x));
                Bs[k][base + i * 4 + 1] = __uint_as_float(cvt_tf32(v.y));
                Bs[k][base + i * 4 + 2] = __uint_as_float(cvt_tf32(v.z));
                Bs[k][base + i * 4 + 3] = __uint_as_float(cvt_tf32(v.w));
            }
        }
        __syncthreads();

#pragma unroll
        for (int ks = 0; ks < 4; ks++) {
            const int k0 = ks * 8;
            unsigned a[4][4];
#pragma unroll
            for (int mi = 0; mi < 4; mi++) {
                int m0 = wm * 64 + mi * 16;
                a[mi][0] = __float_as_uint(As[k0 + tg    ][m0 + g    ]);
                a[mi][1] = __float_as_uint(As[k0 + tg    ][m0 + g + 8]);
                a[mi][2] = __float_as_uint(As[k0 + tg + 4][m0 + g    ]);
                a[mi][3] = __float_as_uint(As[k0 + tg + 4][m0 + g + 8]);
            }
            unsigned b[4][2];
#pragma unroll
            for (int ni = 0; ni < 4; ni++) {
                int n0 = wn * 32 + ni * 8;
                b[ni][0] = __float_as_uint(Bs[k0 + tg    ][n0 + g]);
                b[ni][1] = __float_as_uint(Bs[k0 + tg + 4][n0 + g]);
            }
#pragma unroll
            for (int mi = 0; mi < 4; mi++)
#pragma unroll
                for (int ni = 0; ni < 4; ni++) {
                    asm volatile(
                        "mma.sync.aligned.m16n8k8.row.col.f32.tf32.tf32.f32 "
                        "{%0,%1,%2,%3}, {%4,%5,%6,%7}, {%8,%9}, {%0,%1,%2,%3};"
                        : "+f"(c[mi][ni][0]), "+f"(c[mi][ni][1]),
                          "+f"(c[mi][ni][2]), "+f"(c[mi][ni][3])
                        : "r"(a[mi][0]), "r"(a[mi][1]), "r"(a[mi][2]), "r"(a[mi][3]),
                          "r"(b[ni][0]), "r"(b[ni][1]));
                }
        }
        __syncthreads();
    }

    // epilogue: add bias, store (c0,c1 -> row g; c2,c3 -> row g+8)
#pragma unroll
    for (int ni = 0; ni < 4; ni++) {
        int col = wn * 32 + ni * 8 + tg * 2;
        float bx = bias[col], by = bias[col + 1];
#pragma unroll
        for (int mi = 0; mi < 4; mi++) {
            int rowA = row0 + wm * 64 + mi * 16 + g;
            if (rowA < n) {
                float2 o = make_float2(c[mi][ni][0] + bx, c[mi][ni][1] + by);
                *(float2*)(out + (size_t)rowA * 128 + col) = o;
            }
            int rowB = rowA + 8;
            if (rowB < n) {
                float2 o = make_float2(c[mi][ni][2] + bx, c[mi][ni][3] + by);
                *(float2*)(out + (size_t)rowB * 128 + col) = o;
            }
        }
    }
}

// ---------------- CSR construction --------------------------------------
__global__ void zero_cnt(int n)
{
    int i = blockIdx.x * blockDim.x + threadIdx.x;
    if (i < n) g_cnt[i] = 0;
}

__global__ void hist_kernel(const int* __restrict__ dst, int E)
{
    int i = blockIdx.x * blockDim.x + threadIdx.x;
    if (i < E) atomicAdd(&g_cnt[dst[i]], 1);
}

// Stage 1: per-block reduction of g_cnt chunks (SCAN_BLK elems per block)
__global__ __launch_bounds__(SCAN_BLK) void scan_partial(int n)
{
    __shared__ int sh[SCAN_BLK];
    int i = blockIdx.x * SCAN_BLK + threadIdx.x;
    int v = (i < n) ? g_cnt[i] : 0;
    sh[threadIdx.x] = v;
    __syncthreads();
    for (int off = SCAN_BLK / 2; off > 0; off >>= 1) {
        if (threadIdx.x < off) sh[threadIdx.x] += sh[threadIdx.x + off];
        __syncthreads();
    }
    if (threadIdx.x == 0) g_bsum[blockIdx.x] = sh[0];
}

// Stage 2: single-block exclusive scan of block sums (nb <= 256)
__global__ __launch_bounds__(SCAN_BLK) void scan_bsums(int nb)
{
    __shared__ int sh[SCAN_BLK];
    int t = threadIdx.x;
    int v = (t < nb) ? g_bsum[t] : 0;
    sh[t] = v;
    __syncthreads();
    for (int off = 1; off < SCAN_BLK; off <<= 1) {
        int u = (t >= off) ? sh[t - off] : 0;
        __syncthreads();
        sh[t] += u;
        __syncthreads();
    }
    if (t < nb) g_bsum[t] = sh[t] - v;   // exclusive
}

// Stage 3: per-block exclusive scan of chunk + block offset -> g_off/g_cur
__global__ __launch_bounds__(SCAN_BLK) void scan_final(int n)
{
    __shared__ int sh[SCAN_BLK];
    int i = blockIdx.x * SCAN_BLK + threadIdx.x;
    int t = threadIdx.x;
    int v = (i < n) ? g_cnt[i] : 0;
    sh[t] = v;
    __syncthreads();
    for (int off = 1; off < SCAN_BLK; off <<= 1) {
        int u = (t >= off) ? sh[t - off] : 0;
        __syncthreads();
        sh[t] += u;
        __syncthreads();
    }
    if (i < n) {
        int excl = sh[t] - v + g_bsum[blockIdx.x];
        g_off[i] = excl;
        g_cur[i] = excl;
    }
}

__global__ void scatter_kernel(const int* __restrict__ src,
                               const int* __restrict__ dst, int E)
{
    int i = blockIdx.x * blockDim.x + threadIdx.x;
    if (i < E) {
        int p = atomicAdd(&g_cur[dst[i]], 1);
        g_esrc[p] = src[i];
    }
}

// ---------------- gather: one warp per destination node ------------------
// lane l owns dims [l*4, l*4+4). head = l/4 (4 lanes x 4 dims = 16 dims/head).
__global__ __launch_bounds__(256) void gat_gather(float* __restrict__ out, int n)
{
    int warp = (blockIdx.x * blockDim.x + threadIdx.x) >> 5;
    int lane = threadIdx.x & 31;
    if (warp >= n) return;

    const int t = lane * 4;
    const int start = g_off[warp];
    const int end   = g_cur[warp];   // == g_off + count after scatter

    const float4 q = *(const float4*)(g_Q + (size_t)warp * 128 + t);

    float ax = 0.f, ay = 0.f, az = 0.f, aw = 0.f;
    float den = 0.f;

    int s_next = (start < end) ? g_esrc[start] : 0;
    for (int i = start; i < end; i++) {
        int s = s_next;                    // uniform across warp (broadcast)
        if (i + 1 < end) s_next = g_esrc[i + 1];   // prefetch next index
        const float4 k4 = *(const float4*)(g_K + (size_t)s * 128 + t);
        float p = q.x * k4.x + q.y * k4.y + q.z * k4.z + q.w * k4.w;
        p += __shfl_xor_sync(0xFFFFFFFFu, p, 1);
        p += __shfl_xor_sync(0xFFFFFFFFu, p, 2);
        float e = __expf(p * 0.25f);       // 1/sqrt(D), D=16
        const float4 v4 = *(const float4*)(g_V + (size_t)s * 128 + t);
        ax = fmaf(e, v4.x, ax);
        ay = fmaf(e, v4.y, ay);
        az = fmaf(e, v4.z, az);
        aw = fmaf(e, v4.w, aw);
        den += e;
    }

    float inv = 1.f / den;
    float4 o;
    o.x = ax * inv; o.y = ay * inv; o.z = az * inv; o.w = aw * inv;
    *(float4*)(out + (size_t)warp * 128 + t) = o;
}

// ---------------- launch ------------------------------------------------
extern "C" void kernel_launch(void* const* d_in, const int* in_sizes, int n_in,
                              void* d_out, int out_size)
{
    const float* h  = (const float*)d_in[0];
    const float* wq = (const float*)d_in[1];
    const float* bq = (const float*)d_in[2];
    const float* wk = (const float*)d_in[3];
    const float* bk = (const float*)d_in[4];
    const float* wv = (const float*)d_in[5];
    const float* bv = (const float*)d_in[6];
    const int*  src = (const int*)d_in[7];
    const int*  dst = (const int*)d_in[8];

    const int n = in_sizes[0] / HID;
    const int E = in_sizes[7];
    const int nb = (n + SCAN_BLK - 1) / SCAN_BLK;

    float* out = (float*)d_out;

    // 1) Q,K,V GEMMs (tf32 tensor cores)
    {
        dim3 grid((n + 127) / 128, 3);
        qkv_gemm<<<grid, 256>>>(h, wq, bq, wk, bk, wv, bv, n);
    }
    // 2) CSR build (parallel 3-stage scan)
    zero_cnt<<<(n + 255) / 256, 256>>>(n);
    hist_kernel<<<(E + 255) / 256, 256>>>(dst, E);
    scan_partial<<<nb, SCAN_BLK>>>(n);
    scan_bsums<<<1, SCAN_BLK>>>(nb);
    scan_final<<<nb, SCAN_BLK>>>(n);
    scatter_kernel<<<(E + 255) / 256, 256>>>(src, dst, E);
    // 3) gather (one warp per node, 8 warps/block)
    gat_gather<<<(n + 7) / 8, 256>>>(out, n);
}